// round 2
// baseline (speedup 1.0000x reference)
#include <cuda_runtime.h>
#include <math.h>

// Problem constants (fixed by reference setup)
#define N_NODES   7400000      // 200000 * 37
#define NPG       37

// Scratch accumulator: agg[i] = x[i]*root + conv_bias + sum(msg)
__device__ float g_agg[N_NODES];

// ---------------------------------------------------------------------------
// Kernel 1: init accumulator with x*root + conv_bias (fused, vectorized)
// ---------------------------------------------------------------------------
__global__ void init_kernel(const float* __restrict__ x,
                            const float* __restrict__ root,
                            const float* __restrict__ conv_bias,
                            int n)
{
    int i = blockIdx.x * blockDim.x + threadIdx.x;
    float r  = root[0];
    float cb = conv_bias[0];
    int i4 = i * 4;
    if (i4 + 3 < n) {
        float4 xv = *reinterpret_cast<const float4*>(x + i4);
        float4 o;
        o.x = fmaf(xv.x, r, cb);
        o.y = fmaf(xv.y, r, cb);
        o.z = fmaf(xv.z, r, cb);
        o.w = fmaf(xv.w, r, cb);
        *reinterpret_cast<float4*>(g_agg + i4) = o;
    } else {
        for (int k = i4; k < n; k++) g_agg[k] = fmaf(x[k], r, cb);
    }
}

// ---------------------------------------------------------------------------
// Kernel 2: per-edge MLP + scatter-add.  ew(a) = b2 + sum_j relu(a*W1j+b1j)*W2j
// msg = x[src]*ew  ->  atomicAdd(agg[dst], msg)  (no return value -> REDG)
// ---------------------------------------------------------------------------
__global__ void edge_kernel(const float* __restrict__ ea,
                            const int*   __restrict__ src,
                            const int*   __restrict__ dst,
                            const float* __restrict__ x,
                            const float* __restrict__ W1,
                            const float* __restrict__ b1,
                            const float* __restrict__ W2,
                            const float* __restrict__ b2,
                            int E)
{
    int i = blockIdx.x * blockDim.x + threadIdx.x;
    int i4 = i * 4;
    if (i4 >= E) return;

    float w1[4], c1[4], w2[4];
#pragma unroll
    for (int j = 0; j < 4; j++) { w1[j] = W1[j]; c1[j] = b1[j]; w2[j] = W2[j]; }
    float c2 = b2[0];

    if (i4 + 3 < E) {
        float4 a = *reinterpret_cast<const float4*>(ea + i4);
        int4   s = *reinterpret_cast<const int4*>(src + i4);
        int4   d = *reinterpret_cast<const int4*>(dst + i4);
        float av[4] = {a.x, a.y, a.z, a.w};
        int   sv[4] = {s.x, s.y, s.z, s.w};
        int   dv[4] = {d.x, d.y, d.z, d.w};
        float ew[4];
#pragma unroll
        for (int e = 0; e < 4; e++) {
            float acc = c2;
#pragma unroll
            for (int j = 0; j < 4; j++)
                acc = fmaf(fmaxf(fmaf(av[e], w1[j], c1[j]), 0.0f), w2[j], acc);
            ew[e] = acc;
        }
#pragma unroll
        for (int e = 0; e < 4; e++) {
            float msg = __ldg(x + sv[e]) * ew[e];
            atomicAdd(&g_agg[dv[e]], msg);
        }
    } else {
        for (int k = i4; k < E; k++) {
            float a = ea[k];
            float acc = c2;
#pragma unroll
            for (int j = 0; j < 4; j++)
                acc = fmaf(fmaxf(fmaf(a, w1[j], c1[j]), 0.0f), w2[j], acc);
            float msg = __ldg(x + src[k]) * acc;
            atomicAdd(&g_agg[dst[k]], msg);
        }
    }
}

// ---------------------------------------------------------------------------
// Kernel 3: per-graph MLP (37->8->8->2) + angle epilogue.
// One thread per graph; block tiles 128 graphs into shared (stride 37 is
// coprime with 32 banks -> conflict-free per-thread reads).
// ---------------------------------------------------------------------------
#define GPB 128
__global__ void graph_kernel(const float* __restrict__ Wa,
                             const float* __restrict__ ba,
                             const float* __restrict__ Wb,
                             const float* __restrict__ bb,
                             const float* __restrict__ Wc,
                             const float* __restrict__ bc,
                             float* __restrict__ out,
                             int n_graphs)
{
    __shared__ float sW[296 + 8 + 64 + 8 + 16 + 2];   // 394 floats
    __shared__ float sg[GPB * NPG];

    int tid = threadIdx.x;
    for (int i = tid; i < 394; i += GPB) {
        float v;
        if      (i < 296) v = Wa[i];
        else if (i < 304) v = ba[i - 296];
        else if (i < 368) v = Wb[i - 304];
        else if (i < 376) v = bb[i - 368];
        else if (i < 392) v = Wc[i - 376];
        else              v = bc[i - 392];
        sW[i] = v;
    }

    int gbase = blockIdx.x * GPB;
    int ngb = n_graphs - gbase;
    if (ngb > GPB) ngb = GPB;
    int nload = ngb * NPG;
    const float* srcp = g_agg + (size_t)gbase * NPG;
    for (int i = tid; i < nload; i += GPB) sg[i] = srcp[i];
    __syncthreads();

    int g = gbase + tid;
    if (tid >= ngb || g >= n_graphs) return;

    const float* v = sg + tid * NPG;
    const float* sWa = sW;
    const float* sba = sW + 296;
    const float* sWb = sW + 304;
    const float* sbb = sW + 368;
    const float* sWc = sW + 376;
    const float* sbc = sW + 392;

    float h1[8];
#pragma unroll
    for (int j = 0; j < 8; j++) h1[j] = sba[j];
    for (int k = 0; k < NPG; k++) {
        float vk = v[k];
#pragma unroll
        for (int j = 0; j < 8; j++) h1[j] = fmaf(vk, sWa[k * 8 + j], h1[j]);
    }
#pragma unroll
    for (int j = 0; j < 8; j++) h1[j] = fmaxf(h1[j], 0.0f);

    float h2[8];
#pragma unroll
    for (int j = 0; j < 8; j++) h2[j] = sbb[j];
#pragma unroll
    for (int k = 0; k < 8; k++) {
#pragma unroll
        for (int j = 0; j < 8; j++) h2[j] = fmaf(h1[k], sWb[k * 8 + j], h2[j]);
    }
#pragma unroll
    for (int j = 0; j < 8; j++) h2[j] = fmaxf(h2[j], 0.0f);

    float X = sbc[0], Y = sbc[1];
#pragma unroll
    for (int k = 0; k < 8; k++) {
        X = fmaf(h2[k], sWc[k * 2 + 0], X);
        Y = fmaf(h2[k], sWc[k * 2 + 1], Y);
    }

    float sgn = (Y > 0.0f) ? 1.0f : ((Y < 0.0f) ? -1.0f : 0.0f);
    float angle = atanf(X / Y) + 1.5707963267948966f * sgn + 3.141592653589793f;
    out[g] = angle * 1.909859317102744f;   // 12 / (2*pi)
}

// ---------------------------------------------------------------------------
extern "C" void kernel_launch(void* const* d_in, const int* in_sizes, int n_in,
                              void* d_out, int out_size)
{
    const float* x         = (const float*)d_in[0];
    const float* edge_attr = (const float*)d_in[1];
    const float* W1        = (const float*)d_in[2];
    const float* b1        = (const float*)d_in[3];
    const float* W2        = (const float*)d_in[4];
    const float* b2        = (const float*)d_in[5];
    const float* root      = (const float*)d_in[6];
    const float* conv_bias = (const float*)d_in[7];
    const float* Wa        = (const float*)d_in[8];
    const float* ba        = (const float*)d_in[9];
    const float* Wb        = (const float*)d_in[10];
    const float* bb        = (const float*)d_in[11];
    const float* Wc        = (const float*)d_in[12];
    const float* bc        = (const float*)d_in[13];
    const int*   edge_index= (const int*)d_in[14];

    int N = in_sizes[0];      // node count (x is (N,1))
    int E = in_sizes[1];      // edge count (edge_attr is (E,1))
    int n_graphs = N / NPG;

    const int* src = edge_index;
    const int* dst = edge_index + E;

    float* out = (float*)d_out;

    {
        int threads = 256;
        int work = (N + 3) / 4;
        int blocks = (work + threads - 1) / threads;
        init_kernel<<<blocks, threads>>>(x, root, conv_bias, N);
    }
    {
        int threads = 256;
        int work = (E + 3) / 4;
        int blocks = (work + threads - 1) / threads;
        edge_kernel<<<blocks, threads>>>(edge_attr, src, dst, x,
                                         W1, b1, W2, b2, E);
    }
    {
        int blocks = (n_graphs + GPB - 1) / GPB;
        graph_kernel<<<blocks, GPB>>>(Wa, ba, Wb, bb, Wc, bc, out, n_graphs);
    }
}